// round 5
// baseline (speedup 1.0000x reference)
#include <cuda_runtime.h>
#include <mma.h>
#include <math.h>

using namespace nvcuda;

// ---------------- static problem dims ----------------
#define BB    32
#define HH    56
#define WWD   56
#define CC    384
#define NTOK  (BB * HH * WWD)      // 100352
#define LL    49
#define NWIN  2048
#define C3    1152
#define NHEAD 12
#define HDIM  32

// GEMM tiling
#define TK    16
#define SSTR  20                    // smem row stride (floats)

// ---------------- scratch (device globals; no allocs allowed) ----------------
__device__ float g_yw[(size_t)NTOK * CC];    // layernormed, window-ordered
__device__ float g_qkv[(size_t)NTOK * C3];   // qkv projection, window-ordered
__device__ float g_att[(size_t)NTOK * CC];   // attention output, window-ordered

// ---------------- K1: LayerNorm + window partition ----------------
__global__ void ln_window_kernel(const float* __restrict__ x,
                                 const float* __restrict__ gamma,
                                 const float* __restrict__ beta) {
    int t = blockIdx.x;
    int tid = threadIdx.x;              // 128 threads
    const float* xin = x + (size_t)t * CC;
    float v0 = xin[tid], v1 = xin[tid + 128], v2 = xin[tid + 256];
    float s = v0 + v1 + v2;
    float s2 = v0 * v0 + v1 * v1 + v2 * v2;
    #pragma unroll
    for (int o = 16; o; o >>= 1) {
        s  += __shfl_down_sync(0xffffffffu, s, o);
        s2 += __shfl_down_sync(0xffffffffu, s2, o);
    }
    __shared__ float red[2][4];
    int wid = tid >> 5, lane = tid & 31;
    if (lane == 0) { red[0][wid] = s; red[1][wid] = s2; }
    __syncthreads();
    if (tid == 0) {
        float a = red[0][0] + red[0][1] + red[0][2] + red[0][3];
        float b = red[1][0] + red[1][1] + red[1][2] + red[1][3];
        float mu = a * (1.0f / CC);
        float var = b * (1.0f / CC) - mu * mu;
        red[0][0] = mu;
        red[1][0] = rsqrtf(var + 1e-5f);
    }
    __syncthreads();
    float mu = red[0][0], rs = red[1][0];

    int b_ = t / (HH * WWD);
    int n  = t % (HH * WWD);
    int h = n / WWD, w = n % WWD;
    int wi = h / 7, i = h % 7, wj = w / 7, j = w % 7;
    int row = (b_ * 64 + wi * 8 + wj) * LL + i * 7 + j;
    float* out = g_yw + (size_t)row * CC;
    out[tid]       = (v0 - mu) * rs * gamma[tid]       + beta[tid];
    out[tid + 128] = (v1 - mu) * rs * gamma[tid + 128] + beta[tid + 128];
    out[tid + 256] = (v2 - mu) * rs * gamma[tid + 256] + beta[tid + 256];
}

// ---------------- K2/K4: TF32 wmma GEMM, 128x128 block, 256 thr, double-buffered
// EPI==0: A = g_yw,  write g_qkv, plain + bias
// EPI==1: A = g_att, write d_out with window-reverse + residual + bias
template <int EPI>
__global__ void __launch_bounds__(256, 2) gemm_tf32_kernel(
        const float* __restrict__ Bw,
        const float* __restrict__ bias,
        const float* __restrict__ resid,
        float* __restrict__ Cout,
        int N, int K) {
    __shared__ float As[2][128 * SSTR];
    __shared__ float Bs[2][128 * SSTR];
    const float* A  = (EPI == 0) ? g_yw : g_att;
    float*       Cw = (EPI == 0) ? g_qkv : Cout;

    int tid = threadIdx.x;              // 256 threads, 8 warps
    int warp = tid >> 5;
    int wm = warp >> 1, wn = warp & 1;  // warp tile: rows wm*32..+32, cols wn*64..+64
    int n0 = blockIdx.x * 128;
    int m0 = blockIdx.y * 128;

    // per-thread load coords: 512 float4 per tile / 256 thr = 2 each
    int lr0 = tid >> 2,        lc0 = (tid & 3) * 4;          // rows 0..63
    int lr1 = (tid + 256) >> 2, lc1 = lc0;                   // rows 64..127

    wmma::fragment<wmma::accumulator, 16, 16, 8, float> acc[2][4];
    #pragma unroll
    for (int a = 0; a < 2; a++)
        #pragma unroll
        for (int b = 0; b < 4; b++) wmma::fill_fragment(acc[a][b], 0.0f);

    const int NCH = 384 / TK;           // K == 384 always; 24 chunks

    // prefetch chunk 0
    float4 pa0, pa1, pb0, pb1;
    {
        const float* Ap = A  + (size_t)m0 * K;
        const float* Bp = Bw + (size_t)n0 * K;
        pa0 = *(const float4*)(Ap + (size_t)lr0 * K + lc0);
        pa1 = *(const float4*)(Ap + (size_t)lr1 * K + lc1);
        pb0 = *(const float4*)(Bp + (size_t)lr0 * K + lc0);
        pb1 = *(const float4*)(Bp + (size_t)lr1 * K + lc1);
    }
    // store chunk 0 (convert to tf32 once here)
    {
        float* a0 = &As[0][lr0 * SSTR + lc0];
        a0[0] = wmma::__float_to_tf32(pa0.x); a0[1] = wmma::__float_to_tf32(pa0.y);
        a0[2] = wmma::__float_to_tf32(pa0.z); a0[3] = wmma::__float_to_tf32(pa0.w);
        float* a1 = &As[0][lr1 * SSTR + lc1];
        a1[0] = wmma::__float_to_tf32(pa1.x); a1[1] = wmma::__float_to_tf32(pa1.y);
        a1[2] = wmma::__float_to_tf32(pa1.z); a1[3] = wmma::__float_to_tf32(pa1.w);
        float* b0 = &Bs[0][lr0 * SSTR + lc0];
        b0[0] = wmma::__float_to_tf32(pb0.x); b0[1] = wmma::__float_to_tf32(pb0.y);
        b0[2] = wmma::__float_to_tf32(pb0.z); b0[3] = wmma::__float_to_tf32(pb0.w);
        float* b1 = &Bs[0][lr1 * SSTR + lc1];
        b1[0] = wmma::__float_to_tf32(pb1.x); b1[1] = wmma::__float_to_tf32(pb1.y);
        b1[2] = wmma::__float_to_tf32(pb1.z); b1[3] = wmma::__float_to_tf32(pb1.w);
    }
    __syncthreads();

    for (int kc = 0; kc < NCH; kc++) {
        int cur = kc & 1;
        // prefetch next chunk into registers (overlaps with mma below)
        if (kc + 1 < NCH) {
            int k0 = (kc + 1) * TK;
            const float* Ap = A  + (size_t)m0 * K + k0;
            const float* Bp = Bw + (size_t)n0 * K + k0;
            pa0 = *(const float4*)(Ap + (size_t)lr0 * K + lc0);
            pa1 = *(const float4*)(Ap + (size_t)lr1 * K + lc1);
            pb0 = *(const float4*)(Bp + (size_t)lr0 * K + lc0);
            pb1 = *(const float4*)(Bp + (size_t)lr1 * K + lc1);
        }
        // mma over this chunk
        #pragma unroll
        for (int kk = 0; kk < TK; kk += 8) {
            wmma::fragment<wmma::matrix_a, 16, 16, 8, wmma::precision::tf32, wmma::row_major> af[2];
            wmma::fragment<wmma::matrix_b, 16, 16, 8, wmma::precision::tf32, wmma::col_major> bf[4];
            #pragma unroll
            for (int mi = 0; mi < 2; mi++)
                wmma::load_matrix_sync(af[mi], &As[cur][(wm * 32 + mi * 16) * SSTR + kk], SSTR);
            #pragma unroll
            for (int ni = 0; ni < 4; ni++)
                wmma::load_matrix_sync(bf[ni], &Bs[cur][(wn * 64 + ni * 16) * SSTR + kk], SSTR);
            #pragma unroll
            for (int mi = 0; mi < 2; mi++)
                #pragma unroll
                for (int ni = 0; ni < 4; ni++)
                    wmma::mma_sync(acc[mi][ni], af[mi], bf[ni], acc[mi][ni]);
        }
        // store next chunk
        if (kc + 1 < NCH) {
            int nxt = cur ^ 1;
            float* a0 = &As[nxt][lr0 * SSTR + lc0];
            a0[0] = wmma::__float_to_tf32(pa0.x); a0[1] = wmma::__float_to_tf32(pa0.y);
            a0[2] = wmma::__float_to_tf32(pa0.z); a0[3] = wmma::__float_to_tf32(pa0.w);
            float* a1 = &As[nxt][lr1 * SSTR + lc1];
            a1[0] = wmma::__float_to_tf32(pa1.x); a1[1] = wmma::__float_to_tf32(pa1.y);
            a1[2] = wmma::__float_to_tf32(pa1.z); a1[3] = wmma::__float_to_tf32(pa1.w);
            float* b0 = &Bs[nxt][lr0 * SSTR + lc0];
            b0[0] = wmma::__float_to_tf32(pb0.x); b0[1] = wmma::__float_to_tf32(pb0.y);
            b0[2] = wmma::__float_to_tf32(pb0.z); b0[3] = wmma::__float_to_tf32(pb0.w);
            float* b1 = &Bs[nxt][lr1 * SSTR + lc1];
            b1[0] = wmma::__float_to_tf32(pb1.x); b1[1] = wmma::__float_to_tf32(pb1.y);
            b1[2] = wmma::__float_to_tf32(pb1.z); b1[3] = wmma::__float_to_tf32(pb1.w);
            __syncthreads();
        }
    }

    // ---------------- epilogue: two 128x64 passes staged in As/Bs space ----
    float* Cs = &As[0][0];              // 128*64 floats = 8192 <= 2*2560+... (As[2] = 10240) OK
    #pragma unroll
    for (int half = 0; half < 2; half++) {
        __syncthreads();
        if (wn == half) {
            #pragma unroll
            for (int mi = 0; mi < 2; mi++)
                #pragma unroll
                for (int ni = 0; ni < 4; ni++)
                    wmma::store_matrix_sync(Cs + (wm * 32 + mi * 16) * 64 + ni * 16,
                                            acc[mi][ni], 64, wmma::mem_row_major);
        }
        __syncthreads();
        #pragma unroll
        for (int q = 0; q < 32; q++) {
            int idx = tid + q * 256;    // 8192 elements
            int r = idx >> 6, c = idx & 63;
            int gcol = n0 + half * 64 + c;
            float val = Cs[idx] + bias[gcol];
            int m = m0 + r;
            if (EPI == 0) {
                Cw[(size_t)m * N + gcol] = val;
            } else {
                int win = m / LL, l = m % LL;
                int b_ = win >> 6, wr = win & 63;
                int wi = wr >> 3, wj = wr & 7;
                int i = l / 7, j = l % 7;
                size_t orig = (size_t)b_ * (HH * WWD) + (size_t)(wi * 7 + i) * WWD + (wj * 7 + j);
                size_t off = orig * CC + gcol;
                Cw[off] = resid[off] + val;
            }
        }
    }
}

// ---------------- K3: per-(window, head) attention in fp32 ----------------
__global__ void attn_kernel() {
    __shared__ float qs[LL * 33];
    __shared__ float ks[LL * 33];
    __shared__ float vs[LL * 33];
    __shared__ float ss[LL * 50];
    int win = blockIdx.x;
    int head = blockIdx.y;
    int tid = threadIdx.x;              // 128 threads
    const float scale = 0.17677669529663687f;   // 1/sqrt(32)

    const float* base = g_qkv + (size_t)win * LL * C3 + head * HDIM;
    for (int idx = tid; idx < LL * 8; idx += 128) {
        int l = idx >> 3, d4 = (idx & 7) * 4;
        const float* p = base + (size_t)l * C3;
        float4 q4 = *(const float4*)(p + d4);
        float4 k4 = *(const float4*)(p + 384 + d4);
        float4 v4 = *(const float4*)(p + 768 + d4);
        qs[l * 33 + d4 + 0] = q4.x * scale; qs[l * 33 + d4 + 1] = q4.y * scale;
        qs[l * 33 + d4 + 2] = q4.z * scale; qs[l * 33 + d4 + 3] = q4.w * scale;
        ks[l * 33 + d4 + 0] = k4.x; ks[l * 33 + d4 + 1] = k4.y;
        ks[l * 33 + d4 + 2] = k4.z; ks[l * 33 + d4 + 3] = k4.w;
        vs[l * 33 + d4 + 0] = v4.x; vs[l * 33 + d4 + 1] = v4.y;
        vs[l * 33 + d4 + 2] = v4.z; vs[l * 33 + d4 + 3] = v4.w;
    }
    __syncthreads();

    int warp = tid >> 5, lane = tid & 31;
    bool has2 = lane < 17;
    int j2 = has2 ? (lane + 32) : 48;

    for (int i = warp; i < LL; i += 4) {
        const float* qr = qs + i * 33;
        const float* k0p = ks + lane * 33;
        const float* k1p = ks + j2 * 33;
        float s0 = 0.f, s1 = 0.f;
        #pragma unroll
        for (int d = 0; d < HDIM; d++) {
            float qv = qr[d];
            s0 += qv * k0p[d];
            s1 += qv * k1p[d];
        }
        ss[i * 50 + lane] = s0;
        if (has2) ss[i * 50 + lane + 32] = s1;
    }
    __syncthreads();

    for (int i = warp; i < LL; i += 4) {
        float a = ss[i * 50 + lane];
        float b = has2 ? ss[i * 50 + lane + 32] : -3.0e38f;
        float m = fmaxf(a, b);
        #pragma unroll
        for (int o = 16; o; o >>= 1) m = fmaxf(m, __shfl_xor_sync(0xffffffffu, m, o));
        float e0 = __expf(a - m);
        float e1 = has2 ? __expf(b - m) : 0.f;
        float sm = e0 + e1;
        #pragma unroll
        for (int o = 16; o; o >>= 1) sm += __shfl_xor_sync(0xffffffffu, sm, o);
        float inv = 1.0f / sm;
        ss[i * 50 + lane] = e0 * inv;
        if (has2) ss[i * 50 + lane + 32] = e1 * inv;
    }
    __syncthreads();

    for (int i = warp; i < LL; i += 4) {
        const float* pr = ss + i * 50;
        float o = 0.f;
        #pragma unroll
        for (int j = 0; j < LL; j++) o += pr[j] * vs[j * 33 + lane];
        g_att[((size_t)win * LL + i) * CC + head * HDIM + lane] = o;
    }
}

// ---------------- launch ----------------
extern "C" void kernel_launch(void* const* d_in, const int* in_sizes, int n_in,
                              void* d_out, int out_size) {
    const float* x     = (const float*)d_in[0];
    const float* gamma = (const float*)d_in[1];
    const float* beta  = (const float*)d_in[2];
    const float* w_in  = (const float*)d_in[3];
    const float* b_in  = (const float*)d_in[4];
    const float* w_out = (const float*)d_in[5];
    const float* b_out = (const float*)d_in[6];
    float* out = (float*)d_out;

    ln_window_kernel<<<NTOK, 128>>>(x, gamma, beta);
    gemm_tf32_kernel<0><<<dim3(C3 / 128, NTOK / 128), 256>>>(w_in, b_in, nullptr, nullptr, C3, CC);
    attn_kernel<<<dim3(NWIN, NHEAD), 128>>>();
    gemm_tf32_kernel<1><<<dim3(CC / 128, NTOK / 128), 256>>>(w_out, b_out, x, out, CC, CC);
}

// round 7
// speedup vs baseline: 1.1601x; 1.1601x over previous
#include <cuda_runtime.h>
#include <cuda_bf16.h>
#include <mma.h>
#include <cstdint>
#include <math.h>

using namespace nvcuda;

// ---------------- static problem dims ----------------
#define BB    32
#define HH    56
#define WWD   56
#define CC    384
#define NTOK  (BB * HH * WWD)      // 100352
#define LL    49
#define NWIN  2048
#define C3    1152
#define NHEAD 12
#define HDIM  32

#define TK    32                    // K-chunk
#define SST   40                    // smem row stride in bf16 elements (80B)

// ---------------- scratch (device globals; no allocs allowed) ----------------
__device__ __nv_bfloat16 g_yhi[(size_t)NTOK * CC];
__device__ __nv_bfloat16 g_ylo[(size_t)NTOK * CC];
__device__ float         g_qkv[(size_t)NTOK * C3];
__device__ __nv_bfloat16 g_ahi[(size_t)NTOK * CC];
__device__ __nv_bfloat16 g_alo[(size_t)NTOK * CC];
__device__ __nv_bfloat16 g_wih[(size_t)C3 * CC];
__device__ __nv_bfloat16 g_wil[(size_t)C3 * CC];
__device__ __nv_bfloat16 g_woh[(size_t)CC * CC];
__device__ __nv_bfloat16 g_wol[(size_t)CC * CC];

// ---------------- K0: weight fp32 -> bf16 hi/lo split ----------------
__global__ void wconv_kernel(const float* __restrict__ w_in, const float* __restrict__ w_out) {
    int i = blockIdx.x * 256 + threadIdx.x;
    if (i < C3 * CC) {
        float v = w_in[i];
        __nv_bfloat16 h = __float2bfloat16(v);
        g_wih[i] = h;
        g_wil[i] = __float2bfloat16(v - __bfloat162float(h));
    }
    if (i < CC * CC) {
        float v = w_out[i];
        __nv_bfloat16 h = __float2bfloat16(v);
        g_woh[i] = h;
        g_wol[i] = __float2bfloat16(v - __bfloat162float(h));
    }
}

// ---------------- K1: LayerNorm + window partition + hi/lo split ----------------
__global__ void ln_window_kernel(const float* __restrict__ x,
                                 const float* __restrict__ gamma,
                                 const float* __restrict__ beta) {
    int t = blockIdx.x;
    int tid = threadIdx.x;              // 128 threads
    const float* xin = x + (size_t)t * CC;
    float v0 = xin[tid], v1 = xin[tid + 128], v2 = xin[tid + 256];
    float s = v0 + v1 + v2;
    float s2 = v0 * v0 + v1 * v1 + v2 * v2;
    #pragma unroll
    for (int o = 16; o; o >>= 1) {
        s  += __shfl_down_sync(0xffffffffu, s, o);
        s2 += __shfl_down_sync(0xffffffffu, s2, o);
    }
    __shared__ float red[2][4];
    int wid = tid >> 5, lane = tid & 31;
    if (lane == 0) { red[0][wid] = s; red[1][wid] = s2; }
    __syncthreads();
    if (tid == 0) {
        float a = red[0][0] + red[0][1] + red[0][2] + red[0][3];
        float b = red[1][0] + red[1][1] + red[1][2] + red[1][3];
        float mu = a * (1.0f / CC);
        float var = b * (1.0f / CC) - mu * mu;
        red[0][0] = mu;
        red[1][0] = rsqrtf(var + 1e-5f);
    }
    __syncthreads();
    float mu = red[0][0], rs = red[1][0];

    int b_ = t / (HH * WWD);
    int n  = t % (HH * WWD);
    int h = n / WWD, w = n % WWD;
    int wi = h / 7, i = h % 7, wj = w / 7, j = w % 7;
    size_t row = (size_t)((b_ * 64 + wi * 8 + wj) * LL + i * 7 + j) * CC;
    #pragma unroll
    for (int q = 0; q < 3; q++) {
        int c = tid + q * 128;
        float v = (q == 0) ? v0 : (q == 1) ? v1 : v2;
        float y = (v - mu) * rs * gamma[c] + beta[c];
        __nv_bfloat16 hbf = __float2bfloat16(y);
        g_yhi[row + c] = hbf;
        g_ylo[row + c] = __float2bfloat16(y - __bfloat162float(hbf));
    }
}

// ---------------- cp.async helpers ----------------
__device__ __forceinline__ void cpa16(uint32_t saddr, const void* gptr) {
    asm volatile("cp.async.cg.shared.global [%0], [%1], 16;" :: "r"(saddr), "l"(gptr));
}

// ---------------- K2/K4: bf16 hi/lo-split wmma GEMM, 128x128, cp.async ------
template <int EPI>
__global__ void __launch_bounds__(256, 2) gemm_bf16_kernel(
        const float* __restrict__ bias,
        const float* __restrict__ resid,
        float* __restrict__ Cout) {
    constexpr int NN = (EPI == 0) ? C3 : CC;
    // 4 tiles (Ah, Al, Bh, Bl), each 128 x SST bf16 = 10240 B -> 40960 B total
    __shared__ __align__(16) char smraw[4 * 128 * SST * 2];
    __nv_bfloat16* tile[4];
    #pragma unroll
    for (int t = 0; t < 4; t++) tile[t] = (__nv_bfloat16*)(smraw + t * (128 * SST * 2));

    const __nv_bfloat16* Ah = (EPI == 0) ? g_yhi : g_ahi;
    const __nv_bfloat16* Al = (EPI == 0) ? g_ylo : g_alo;
    const __nv_bfloat16* Bh = (EPI == 0) ? g_wih : g_woh;
    const __nv_bfloat16* Bl = (EPI == 0) ? g_wil : g_wol;
    float* Cw = (EPI == 0) ? g_qkv : Cout;

    const int tid = threadIdx.x;        // 256 threads, 8 warps
    const int warp = tid >> 5;
    const int wm = warp >> 1;           // 0..3 : rows wm*32..+32
    const int wn = warp & 1;            // 0..1 : cols wn*64..+64
    const int n0 = blockIdx.x * 128;
    const int m0 = blockIdx.y * 128;

    // per-thread copy coords: each tile 128 rows x 32 bf16 = 128 rows x 64B; 2 x 16B segs/thread
    const int r0 = tid >> 1, s0 = (tid & 1) * 2;

    wmma::fragment<wmma::accumulator, 16, 16, 16, float> acc[2][4];
    #pragma unroll
    for (int a = 0; a < 2; a++)
        #pragma unroll
        for (int b = 0; b < 4; b++) wmma::fill_fragment(acc[a][b], 0.0f);

    const int NCH = CC / TK;            // 12

    for (int kc = 0; kc < NCH; kc++) {
        const int k0 = kc * TK;
        const __nv_bfloat16* gsrc[4] = {
            Ah + (size_t)(m0 + r0) * CC + k0,
            Al + (size_t)(m0 + r0) * CC + k0,
            Bh + (size_t)(n0 + r0) * CC + k0,
            Bl + (size_t)(n0 + r0) * CC + k0 };
        #pragma unroll
        for (int t = 0; t < 4; t++) {
            uint32_t sa = (uint32_t)__cvta_generic_to_shared(tile[t] + r0 * SST + s0 * 8);
            cpa16(sa, gsrc[t] + s0 * 8);
            cpa16(sa + 16, gsrc[t] + s0 * 8 + 8);
        }
        asm volatile("cp.async.commit_group;" ::: "memory");
        asm volatile("cp.async.wait_group 0;" ::: "memory");
        __syncthreads();
        #pragma unroll
        for (int kk = 0; kk < TK; kk += 16) {
            wmma::fragment<wmma::matrix_a, 16, 16, 16, __nv_bfloat16, wmma::row_major> ah[2], al[2];
            wmma::fragment<wmma::matrix_b, 16, 16, 16, __nv_bfloat16, wmma::col_major> bh[4], bl[4];
            #pragma unroll
            for (int mi = 0; mi < 2; mi++) {
                wmma::load_matrix_sync(ah[mi], tile[0] + (wm * 32 + mi * 16) * SST + kk, SST);
                wmma::load_matrix_sync(al[mi], tile[1] + (wm * 32 + mi * 16) * SST + kk, SST);
            }
            #pragma unroll
            for (int ni = 0; ni < 4; ni++) {
                wmma::load_matrix_sync(bh[ni], tile[2] + (wn * 64 + ni * 16) * SST + kk, SST);
                wmma::load_matrix_sync(bl[ni], tile[3] + (wn * 64 + ni * 16) * SST + kk, SST);
            }
            #pragma unroll
            for (int mi = 0; mi < 2; mi++)
                #pragma unroll
                for (int ni = 0; ni < 4; ni++) {
                    wmma::mma_sync(acc[mi][ni], ah[mi], bh[ni], acc[mi][ni]);
                    wmma::mma_sync(acc[mi][ni], ah[mi], bl[ni], acc[mi][ni]);
                    wmma::mma_sync(acc[mi][ni], al[mi], bh[ni], acc[mi][ni]);
                }
        }
        __syncthreads();
    }

    // ---------------- epilogue: two 128x64 halves staged in smem ----------------
    float* Cs = (float*)smraw;          // 32768 B, fits in 40960
    #pragma unroll
    for (int half = 0; half < 2; half++) {
        __syncthreads();
        if (wn == half) {
            #pragma unroll
            for (int mi = 0; mi < 2; mi++)
                #pragma unroll
                for (int ni = 0; ni < 4; ni++)
                    wmma::store_matrix_sync(Cs + (wm * 32 + mi * 16) * 64 + ni * 16,
                                            acc[mi][ni], 64, wmma::mem_row_major);
        }
        __syncthreads();
        #pragma unroll
        for (int q = 0; q < 32; q++) {
            int idx = tid + q * 256;    // 8192 elements
            int r = idx >> 6, c = idx & 63;
            int gcol = n0 + half * 64 + c;
            float val = Cs[idx] + bias[gcol];
            int m = m0 + r;
            if (EPI == 0) {
                Cw[(size_t)m * NN + gcol] = val;
            } else {
                int win = m / LL, l = m % LL;
                int b_ = win >> 6, wr = win & 63;
                int wi = wr >> 3, wj = wr & 7;
                int i = l / 7, j = l % 7;
                size_t orig = (size_t)b_ * (HH * WWD) + (size_t)(wi * 7 + i) * WWD + (wj * 7 + j);
                size_t off = orig * CC + gcol;
                Cw[off] = resid[off] + val;
            }
        }
    }
}

// ---------------- K3: per-(window, head) attention in fp32 ----------------
__global__ void attn_kernel() {
    __shared__ float qs[LL * 33];
    __shared__ float ks[LL * 33];
    __shared__ float vs[LL * 33];
    __shared__ float ss[LL * 50];
    int win = blockIdx.x;
    int head = blockIdx.y;
    int tid = threadIdx.x;              // 128 threads
    const float scale = 0.17677669529663687f;   // 1/sqrt(32)

    const float* base = g_qkv + (size_t)win * LL * C3 + head * HDIM;
    for (int idx = tid; idx < LL * 8; idx += 128) {
        int l = idx >> 3, d4 = (idx & 7) * 4;
        const float* p = base + (size_t)l * C3;
        float4 q4 = *(const float4*)(p + d4);
        float4 k4 = *(const float4*)(p + 384 + d4);
        float4 v4 = *(const float4*)(p + 768 + d4);
        qs[l * 33 + d4 + 0] = q4.x * scale; qs[l * 33 + d4 + 1] = q4.y * scale;
        qs[l * 33 + d4 + 2] = q4.z * scale; qs[l * 33 + d4 + 3] = q4.w * scale;
        ks[l * 33 + d4 + 0] = k4.x; ks[l * 33 + d4 + 1] = k4.y;
        ks[l * 33 + d4 + 2] = k4.z; ks[l * 33 + d4 + 3] = k4.w;
        vs[l * 33 + d4 + 0] = v4.x; vs[l * 33 + d4 + 1] = v4.y;
        vs[l * 33 + d4 + 2] = v4.z; vs[l * 33 + d4 + 3] = v4.w;
    }
    __syncthreads();

    int warp = tid >> 5, lane = tid & 31;
    bool has2 = lane < 17;
    int j2 = has2 ? (lane + 32) : 48;

    for (int i = warp; i < LL; i += 4) {
        const float* qr = qs + i * 33;
        const float* k0p = ks + lane * 33;
        const float* k1p = ks + j2 * 33;
        float s0 = 0.f, s1 = 0.f;
        #pragma unroll
        for (int d = 0; d < HDIM; d++) {
            float qv = qr[d];
            s0 += qv * k0p[d];
            s1 += qv * k1p[d];
        }
        ss[i * 50 + lane] = s0;
        if (has2) ss[i * 50 + lane + 32] = s1;
    }
    __syncthreads();

    for (int i = warp; i < LL; i += 4) {
        float a = ss[i * 50 + lane];
        float b = has2 ? ss[i * 50 + lane + 32] : -3.0e38f;
        float m = fmaxf(a, b);
        #pragma unroll
        for (int o = 16; o; o >>= 1) m = fmaxf(m, __shfl_xor_sync(0xffffffffu, m, o));
        float e0 = __expf(a - m);
        float e1 = has2 ? __expf(b - m) : 0.f;
        float sm = e0 + e1;
        #pragma unroll
        for (int o = 16; o; o >>= 1) sm += __shfl_xor_sync(0xffffffffu, sm, o);
        float inv = 1.0f / sm;
        ss[i * 50 + lane] = e0 * inv;
        if (has2) ss[i * 50 + lane + 32] = e1 * inv;
    }
    __syncthreads();

    for (int i = warp; i < LL; i += 4) {
        const float* pr = ss + i * 50;
        float o = 0.f;
        #pragma unroll
        for (int j = 0; j < LL; j++) o += pr[j] * vs[j * 33 + lane];
        size_t off = ((size_t)win * LL + i) * CC + head * HDIM + lane;
        __nv_bfloat16 h = __float2bfloat16(o);
        g_ahi[off] = h;
        g_alo[off] = __float2bfloat16(o - __bfloat162float(h));
    }
}

// ---------------- launch ----------------
extern "C" void kernel_launch(void* const* d_in, const int* in_sizes, int n_in,
                              void* d_out, int out_size) {
    const float* x     = (const float*)d_in[0];
    const float* gamma = (const float*)d_in[1];
    const float* beta  = (const float*)d_in[2];
    const float* w_in  = (const float*)d_in[3];
    const float* b_in  = (const float*)d_in[4];
    const float* w_out = (const float*)d_in[5];
    const float* b_out = (const float*)d_in[6];
    float* out = (float*)d_out;

    wconv_kernel<<<(C3 * CC + 255) / 256, 256>>>(w_in, w_out);
    ln_window_kernel<<<NTOK, 128>>>(x, gamma, beta);
    gemm_bf16_kernel<0><<<dim3(C3 / 128, NTOK / 128), 256>>>(b_in, nullptr, nullptr);
    attn_kernel<<<dim3(NWIN, NHEAD), 128>>>();
    gemm_bf16_kernel<1><<<dim3(CC / 128, NTOK / 128), 256>>>(b_out, x, out);
}

// round 9
// speedup vs baseline: 1.1781x; 1.0156x over previous
#include <cuda_runtime.h>
#include <cuda_bf16.h>
#include <mma.h>
#include <cstdint>
#include <math.h>

using namespace nvcuda;

// ---------------- static problem dims ----------------
#define BB    32
#define HH    56
#define WWD   56
#define CC    384
#define NTOK  (BB * HH * WWD)      // 100352
#define LL    49
#define NWIN  2048
#define C3    1152
#define NHEAD 12
#define HDIM  32

#define TK    32                    // GEMM K-chunk
#define SST   40                    // GEMM smem row stride (bf16)
#define TILEB (128 * SST * 2)       // 10240 B per tile
#define GSMEM (2 * 4 * TILEB)       // 81920 B dynamic

// ---------------- scratch (device globals; no allocs allowed) ----------------
__device__ __nv_bfloat16 g_yhi[(size_t)NTOK * CC];
__device__ __nv_bfloat16 g_ylo[(size_t)NTOK * CC];
__device__ float         g_qkv[(size_t)NTOK * C3];
__device__ __nv_bfloat16 g_ahi[(size_t)NTOK * CC];
__device__ __nv_bfloat16 g_alo[(size_t)NTOK * CC];
__device__ __nv_bfloat16 g_wih[(size_t)C3 * CC];
__device__ __nv_bfloat16 g_wil[(size_t)C3 * CC];
__device__ __nv_bfloat16 g_woh[(size_t)CC * CC];
__device__ __nv_bfloat16 g_wol[(size_t)CC * CC];

// ---------------- K0: weight fp32 -> bf16 hi/lo split ----------------
__global__ void wconv_kernel(const float* __restrict__ w_in, const float* __restrict__ w_out) {
    int i = blockIdx.x * 256 + threadIdx.x;
    if (i < C3 * CC) {
        float v = w_in[i];
        __nv_bfloat16 h = __float2bfloat16(v);
        g_wih[i] = h;
        g_wil[i] = __float2bfloat16(v - __bfloat162float(h));
    }
    if (i < CC * CC) {
        float v = w_out[i];
        __nv_bfloat16 h = __float2bfloat16(v);
        g_woh[i] = h;
        g_wol[i] = __float2bfloat16(v - __bfloat162float(h));
    }
}

// ---------------- K1: LayerNorm + window partition + hi/lo split ----------------
__global__ void ln_window_kernel(const float* __restrict__ x,
                                 const float* __restrict__ gamma,
                                 const float* __restrict__ beta) {
    int t = blockIdx.x;
    int tid = threadIdx.x;              // 128 threads
    const float* xin = x + (size_t)t * CC;
    float v0 = xin[tid], v1 = xin[tid + 128], v2 = xin[tid + 256];
    float s = v0 + v1 + v2;
    float s2 = v0 * v0 + v1 * v1 + v2 * v2;
    #pragma unroll
    for (int o = 16; o; o >>= 1) {
        s  += __shfl_down_sync(0xffffffffu, s, o);
        s2 += __shfl_down_sync(0xffffffffu, s2, o);
    }
    __shared__ float red[2][4];
    int wid = tid >> 5, lane = tid & 31;
    if (lane == 0) { red[0][wid] = s; red[1][wid] = s2; }
    __syncthreads();
    if (tid == 0) {
        float a = red[0][0] + red[0][1] + red[0][2] + red[0][3];
        float b = red[1][0] + red[1][1] + red[1][2] + red[1][3];
        float mu = a * (1.0f / CC);
        float var = b * (1.0f / CC) - mu * mu;
        red[0][0] = mu;
        red[1][0] = rsqrtf(var + 1e-5f);
    }
    __syncthreads();
    float mu = red[0][0], rs = red[1][0];

    int b_ = t / (HH * WWD);
    int n  = t % (HH * WWD);
    int h = n / WWD, w = n % WWD;
    int wi = h / 7, i = h % 7, wj = w / 7, j = w % 7;
    size_t row = (size_t)((b_ * 64 + wi * 8 + wj) * LL + i * 7 + j) * CC;
    #pragma unroll
    for (int q = 0; q < 3; q++) {
        int c = tid + q * 128;
        float v = (q == 0) ? v0 : (q == 1) ? v1 : v2;
        float y = (v - mu) * rs * gamma[c] + beta[c];
        __nv_bfloat16 hbf = __float2bfloat16(y);
        g_yhi[row + c] = hbf;
        g_ylo[row + c] = __float2bfloat16(y - __bfloat162float(hbf));
    }
}

// ---------------- cp.async helpers ----------------
__device__ __forceinline__ void cpa16(uint32_t saddr, const void* gptr) {
    asm volatile("cp.async.cg.shared.global [%0], [%1], 16;" :: "r"(saddr), "l"(gptr));
}

// ---------------- K2/K4: bf16 hi/lo wmma GEMM, 128x128, 2-stage cp.async ----
template <int EPI>
__global__ void __launch_bounds__(256, 2) gemm_bf16_kernel(
        const float* __restrict__ bias,
        const float* __restrict__ resid,
        float* __restrict__ Cout) {
    constexpr int NN = (EPI == 0) ? C3 : CC;
    extern __shared__ __align__(16) char smraw[];
    __nv_bfloat16* stage[2][4];
    #pragma unroll
    for (int s = 0; s < 2; s++)
        #pragma unroll
        for (int t = 0; t < 4; t++)
            stage[s][t] = (__nv_bfloat16*)(smraw + (s * 4 + t) * TILEB);

    const __nv_bfloat16* Ah = (EPI == 0) ? g_yhi : g_ahi;
    const __nv_bfloat16* Al = (EPI == 0) ? g_ylo : g_alo;
    const __nv_bfloat16* Bh = (EPI == 0) ? g_wih : g_woh;
    const __nv_bfloat16* Bl = (EPI == 0) ? g_wil : g_wol;
    float* Cw = (EPI == 0) ? g_qkv : Cout;

    const int tid = threadIdx.x;        // 256 threads, 8 warps
    const int warp = tid >> 5;
    const int wm = warp >> 1;
    const int wn = warp & 1;
    const int n0 = blockIdx.x * 128;
    const int m0 = blockIdx.y * 128;

    const int r0 = tid >> 1, s0 = (tid & 1) * 2;

    wmma::fragment<wmma::accumulator, 16, 16, 16, float> acc[2][4];
    #pragma unroll
    for (int a = 0; a < 2; a++)
        #pragma unroll
        for (int b = 0; b < 4; b++) wmma::fill_fragment(acc[a][b], 0.0f);

    const int NCH = CC / TK;            // 12

    auto issue_copy = [&](int kc, int st) {
        const int k0 = kc * TK;
        const __nv_bfloat16* gsrc[4] = {
            Ah + (size_t)(m0 + r0) * CC + k0,
            Al + (size_t)(m0 + r0) * CC + k0,
            Bh + (size_t)(n0 + r0) * CC + k0,
            Bl + (size_t)(n0 + r0) * CC + k0 };
        #pragma unroll
        for (int t = 0; t < 4; t++) {
            uint32_t sa = (uint32_t)__cvta_generic_to_shared(stage[st][t] + r0 * SST + s0 * 8);
            cpa16(sa, gsrc[t] + s0 * 8);
            cpa16(sa + 16, gsrc[t] + s0 * 8 + 8);
        }
        asm volatile("cp.async.commit_group;" ::: "memory");
    };

    issue_copy(0, 0);

    for (int kc = 0; kc < NCH; kc++) {
        const int cur = kc & 1;
        if (kc + 1 < NCH) {
            issue_copy(kc + 1, cur ^ 1);
            asm volatile("cp.async.wait_group 1;" ::: "memory");
        } else {
            asm volatile("cp.async.wait_group 0;" ::: "memory");
        }
        __syncthreads();
        const __nv_bfloat16* sAh = stage[cur][0];
        const __nv_bfloat16* sAl = stage[cur][1];
        const __nv_bfloat16* sBh = stage[cur][2];
        const __nv_bfloat16* sBl = stage[cur][3];
        #pragma unroll
        for (int kk = 0; kk < TK; kk += 16) {
            wmma::fragment<wmma::matrix_a, 16, 16, 16, __nv_bfloat16, wmma::row_major> ah[2], al[2];
            wmma::fragment<wmma::matrix_b, 16, 16, 16, __nv_bfloat16, wmma::col_major> bh[4], bl[4];
            #pragma unroll
            for (int mi = 0; mi < 2; mi++) {
                wmma::load_matrix_sync(ah[mi], sAh + (wm * 32 + mi * 16) * SST + kk, SST);
                wmma::load_matrix_sync(al[mi], sAl + (wm * 32 + mi * 16) * SST + kk, SST);
            }
            #pragma unroll
            for (int ni = 0; ni < 4; ni++) {
                wmma::load_matrix_sync(bh[ni], sBh + (wn * 64 + ni * 16) * SST + kk, SST);
                wmma::load_matrix_sync(bl[ni], sBl + (wn * 64 + ni * 16) * SST + kk, SST);
            }
            #pragma unroll
            for (int mi = 0; mi < 2; mi++)
                #pragma unroll
                for (int ni = 0; ni < 4; ni++) {
                    wmma::mma_sync(acc[mi][ni], ah[mi], bh[ni], acc[mi][ni]);
                    wmma::mma_sync(acc[mi][ni], ah[mi], bl[ni], acc[mi][ni]);
                    wmma::mma_sync(acc[mi][ni], al[mi], bh[ni], acc[mi][ni]);
                }
        }
        __syncthreads();
    }

    // epilogue: two 128x64 halves staged in smem
    float* Cs = (float*)smraw;
    #pragma unroll
    for (int half = 0; half < 2; half++) {
        __syncthreads();
        if (wn == half) {
            #pragma unroll
            for (int mi = 0; mi < 2; mi++)
                #pragma unroll
                for (int ni = 0; ni < 4; ni++)
                    wmma::store_matrix_sync(Cs + (wm * 32 + mi * 16) * 64 + ni * 16,
                                            acc[mi][ni], 64, wmma::mem_row_major);
        }
        __syncthreads();
        #pragma unroll
        for (int q = 0; q < 32; q++) {
            int idx = tid + q * 256;
            int r = idx >> 6, c = idx & 63;
            int gcol = n0 + half * 64 + c;
            float val = Cs[idx] + bias[gcol];
            int m = m0 + r;
            if (EPI == 0) {
                Cw[(size_t)m * NN + gcol] = val;
            } else {
                int win = m / LL, l = m % LL;
                int b_ = win >> 6, wr = win & 63;
                int wi = wr >> 3, wj = wr & 7;
                int i = l / 7, j = l % 7;
                size_t orig = (size_t)b_ * (HH * WWD) + (size_t)(wi * 7 + i) * WWD + (wj * 7 + j);
                size_t off = orig * CC + gcol;
                Cw[off] = resid[off] + val;
            }
        }
    }
}

// ---------------- K3: attention, 4-row register blocking + LDS.128 ----------
// qs/ks stride 36 (36%32=4 -> conflict-free float4), vsT stride 52 (52%32=20),
// ss stride 52 (cols 49..51 zero-padded)
__global__ void attn_kernel() {
    __shared__ __align__(16) float qs[LL * 36];
    __shared__ __align__(16) float ks[LL * 36];
    __shared__ __align__(16) float vsT[HDIM * 52];
    __shared__ __align__(16) float ss[LL * 52];
    int win = blockIdx.x;
    int head = blockIdx.y;
    int tid = threadIdx.x;              // 128 threads
    const float scale = 0.17677669529663687f;   // 1/sqrt(32)

    // zero pads (ss cols 49..51 for all rows; vsT cols 49..51 for all d)
    for (int idx = tid; idx < LL * 3; idx += 128)
        ss[(idx / 3) * 52 + 49 + idx % 3] = 0.f;
    if (tid < HDIM * 3)
        vsT[(tid / 3) * 52 + 49 + tid % 3] = 0.f;

    const float* base = g_qkv + (size_t)win * LL * C3 + head * HDIM;
    for (int idx = tid; idx < LL * 8; idx += 128) {
        int l = idx >> 3, d4 = (idx & 7) * 4;
        const float* p = base + (size_t)l * C3;
        float4 q4 = *(const float4*)(p + d4);
        float4 k4 = *(const float4*)(p + 384 + d4);
        float4 v4 = *(const float4*)(p + 768 + d4);
        qs[l * 36 + d4 + 0] = q4.x * scale; qs[l * 36 + d4 + 1] = q4.y * scale;
        qs[l * 36 + d4 + 2] = q4.z * scale; qs[l * 36 + d4 + 3] = q4.w * scale;
        ks[l * 36 + d4 + 0] = k4.x; ks[l * 36 + d4 + 1] = k4.y;
        ks[l * 36 + d4 + 2] = k4.z; ks[l * 36 + d4 + 3] = k4.w;
        vsT[(d4 + 0) * 52 + l] = v4.x;
        vsT[(d4 + 1) * 52 + l] = v4.y;
        vsT[(d4 + 2) * 52 + l] = v4.z;
        vsT[(d4 + 3) * 52 + l] = v4.w;
    }
    __syncthreads();

    int warp = tid >> 5, lane = tid & 31;
    bool has2 = lane < 17;
    int j2 = has2 ? (lane + 32) : 48;

    // ---- scores: 4 query rows per pass ----
    for (int g = warp; g < 13; g += 4) {
        float acc[4][2] = {{0.f,0.f},{0.f,0.f},{0.f,0.f},{0.f,0.f}};
        const float* k0p = ks + lane * 36;
        const float* k1p = ks + j2 * 36;
        #pragma unroll
        for (int d4 = 0; d4 < HDIM; d4 += 4) {
            float4 k0 = *(const float4*)(k0p + d4);
            float4 k1 = *(const float4*)(k1p + d4);
            #pragma unroll
            for (int rr = 0; rr < 4; rr++) {
                int row = g * 4 + rr;
                int rq = row < LL ? row : LL - 1;
                float4 q = *(const float4*)(qs + rq * 36 + d4);
                acc[rr][0] += q.x * k0.x + q.y * k0.y + q.z * k0.z + q.w * k0.w;
                acc[rr][1] += q.x * k1.x + q.y * k1.y + q.z * k1.z + q.w * k1.w;
            }
        }
        #pragma unroll
        for (int rr = 0; rr < 4; rr++) {
            int row = g * 4 + rr;
            if (row < LL) {
                ss[row * 52 + lane] = acc[rr][0];
                if (has2) ss[row * 52 + lane + 32] = acc[rr][1];
            }
        }
    }
    __syncthreads();

    // ---- softmax per row ----
    for (int i = warp; i < LL; i += 4) {
        float a = ss[i * 52 + lane];
        float b = has2 ? ss[i * 52 + lane + 32] : -3.0e38f;
        float m = fmaxf(a, b);
        #pragma unroll
        for (int o = 16; o; o >>= 1) m = fmaxf(m, __shfl_xor_sync(0xffffffffu, m, o));
        float e0 = __expf(a - m);
        float e1 = has2 ? __expf(b - m) : 0.f;
        float sm = e0 + e1;
        #pragma unroll
        for (int o = 16; o; o >>= 1) sm += __shfl_xor_sync(0xffffffffu, sm, o);
        float inv = 1.0f / sm;
        ss[i * 52 + lane] = e0 * inv;
        if (has2) ss[i * 52 + lane + 32] = e1 * inv;
    }
    __syncthreads();

    // ---- O = P @ V: 4 rows per pass, lane = head dim ----
    for (int g = warp; g < 13; g += 4) {
        float acc[4] = {0.f, 0.f, 0.f, 0.f};
        const float* vp = vsT + lane * 52;
        #pragma unroll
        for (int j4 = 0; j4 < 52; j4 += 4) {
            float4 v = *(const float4*)(vp + j4);
            #pragma unroll
            for (int rr = 0; rr < 4; rr++) {
                int row = g * 4 + rr;
                int rq = row < LL ? row : LL - 1;
                float4 p = *(const float4*)(ss + rq * 52 + j4);
                acc[rr] += p.x * v.x + p.y * v.y + p.z * v.z + p.w * v.w;
            }
        }
        #pragma unroll
        for (int rr = 0; rr < 4; rr++) {
            int row = g * 4 + rr;
            if (row < LL) {
                size_t off = ((size_t)win * LL + row) * CC + head * HDIM + lane;
                __nv_bfloat16 h = __float2bfloat16(acc[rr]);
                g_ahi[off] = h;
                g_alo[off] = __float2bfloat16(acc[rr] - __bfloat162float(h));
            }
        }
    }
}

// ---------------- launch ----------------
extern "C" void kernel_launch(void* const* d_in, const int* in_sizes, int n_in,
                              void* d_out, int out_size) {
    const float* x     = (const float*)d_in[0];
    const float* gamma = (const float*)d_in[1];
    const float* beta  = (const float*)d_in[2];
    const float* w_in  = (const float*)d_in[3];
    const float* b_in  = (const float*)d_in[4];
    const float* w_out = (const float*)d_in[5];
    const float* b_out = (const float*)d_in[6];
    float* out = (float*)d_out;

    cudaFuncSetAttribute(gemm_bf16_kernel<0>,
                         cudaFuncAttributeMaxDynamicSharedMemorySize, GSMEM);
    cudaFuncSetAttribute(gemm_bf16_kernel<1>,
                         cudaFuncAttributeMaxDynamicSharedMemorySize, GSMEM);

    wconv_kernel<<<(C3 * CC + 255) / 256, 256>>>(w_in, w_out);
    ln_window_kernel<<<NTOK, 128>>>(x, gamma, beta);
    gemm_bf16_kernel<0><<<dim3(C3 / 128, NTOK / 128), 256, GSMEM>>>(b_in, nullptr, nullptr);
    attn_kernel<<<dim3(NWIN, NHEAD), 128>>>();
    gemm_bf16_kernel<1><<<dim3(CC / 128, NTOK / 128), 256, GSMEM>>>(b_out, x, out);
}

// round 10
// speedup vs baseline: 1.9684x; 1.6707x over previous
#include <cuda_runtime.h>
#include <cuda_fp16.h>
#include <mma.h>
#include <cstdint>
#include <math.h>

using namespace nvcuda;

// ---------------- static problem dims ----------------
#define BB    32
#define HH    56
#define WWD   56
#define CC    384
#define NTOK  (BB * HH * WWD)      // 100352
#define LL    49
#define NWIN  2048
#define C3    1152
#define NHEAD 12
#define HDIM  32

#define TK    32                    // GEMM K-chunk
#define SST   40                    // GEMM smem row stride (fp16)
#define TILEB (128 * SST * 2)       // 10240 B per tile
#define GSMEM (2 * 2 * TILEB)       // 40960 B dynamic (2 stages x {A,B})

// ---------------- scratch (device globals; no allocs allowed) ----------------
__device__ __half g_yh[(size_t)NTOK * CC];    // LN output fp16, window-ordered
__device__ float  g_qkv[(size_t)NTOK * C3];   // qkv fp32, window-ordered
__device__ __half g_a[(size_t)NTOK * CC];     // attention out fp16
__device__ __half g_wi[(size_t)C3 * CC];      // w_in fp16
__device__ __half g_wo[(size_t)CC * CC];      // w_out fp16

// ---------------- K0: weight fp32 -> fp16 ----------------
__global__ void wconv_kernel(const float* __restrict__ w_in, const float* __restrict__ w_out) {
    int i = blockIdx.x * 256 + threadIdx.x;
    if (i < C3 * CC) g_wi[i] = __float2half(w_in[i]);
    if (i < CC * CC) g_wo[i] = __float2half(w_out[i]);
}

// ---------------- K1: LayerNorm + window partition -> fp16 ----------------
__global__ void ln_window_kernel(const float* __restrict__ x,
                                 const float* __restrict__ gamma,
                                 const float* __restrict__ beta) {
    int t = blockIdx.x;
    int tid = threadIdx.x;              // 128 threads
    const float* xin = x + (size_t)t * CC;
    float v0 = xin[tid], v1 = xin[tid + 128], v2 = xin[tid + 256];
    float s = v0 + v1 + v2;
    float s2 = v0 * v0 + v1 * v1 + v2 * v2;
    #pragma unroll
    for (int o = 16; o; o >>= 1) {
        s  += __shfl_down_sync(0xffffffffu, s, o);
        s2 += __shfl_down_sync(0xffffffffu, s2, o);
    }
    __shared__ float red[2][4];
    int wid = tid >> 5, lane = tid & 31;
    if (lane == 0) { red[0][wid] = s; red[1][wid] = s2; }
    __syncthreads();
    if (tid == 0) {
        float a = red[0][0] + red[0][1] + red[0][2] + red[0][3];
        float b = red[1][0] + red[1][1] + red[1][2] + red[1][3];
        float mu = a * (1.0f / CC);
        float var = b * (1.0f / CC) - mu * mu;
        red[0][0] = mu;
        red[1][0] = rsqrtf(var + 1e-5f);
    }
    __syncthreads();
    float mu = red[0][0], rs = red[1][0];

    int b_ = t / (HH * WWD);
    int n  = t % (HH * WWD);
    int h = n / WWD, w = n % WWD;
    int wi = h / 7, i = h % 7, wj = w / 7, j = w % 7;
    size_t row = (size_t)((b_ * 64 + wi * 8 + wj) * LL + i * 7 + j) * CC;
    #pragma unroll
    for (int q = 0; q < 3; q++) {
        int c = tid + q * 128;
        float v = (q == 0) ? v0 : (q == 1) ? v1 : v2;
        g_yh[row + c] = __float2half((v - mu) * rs * gamma[c] + beta[c]);
    }
}

// ---------------- cp.async helpers ----------------
__device__ __forceinline__ void cpa16(uint32_t saddr, const void* gptr) {
    asm volatile("cp.async.cg.shared.global [%0], [%1], 16;" :: "r"(saddr), "l"(gptr));
}

// ---------------- K2/K4: fp16 wmma GEMM, 128x128, 2-stage cp.async ----------
// EPI==0: A=g_yh, B=g_wi, N=1152, write g_qkv (+bias)
// EPI==1: A=g_a,  B=g_wo, N=384,  write d_out (+bias, window reverse, residual)
template <int EPI>
__global__ void __launch_bounds__(256, 2) gemm_fp16_kernel(
        const float* __restrict__ bias,
        const float* __restrict__ resid,
        float* __restrict__ Cout) {
    constexpr int NN = (EPI == 0) ? C3 : CC;
    extern __shared__ __align__(16) char smraw[];
    __half* stage[2][2];
    #pragma unroll
    for (int s = 0; s < 2; s++)
        #pragma unroll
        for (int t = 0; t < 2; t++)
            stage[s][t] = (__half*)(smraw + (s * 2 + t) * TILEB);

    const __half* A = (EPI == 0) ? g_yh : g_a;
    const __half* B = (EPI == 0) ? g_wi : g_wo;
    float* Cw = (EPI == 0) ? g_qkv : Cout;

    const int tid = threadIdx.x;        // 256 threads, 8 warps
    const int warp = tid >> 5;
    const int wm = warp >> 1;           // rows wm*32..+32
    const int wn = warp & 1;            // cols wn*64..+64
    const int n0 = blockIdx.x * 128;
    const int m0 = blockIdx.y * 128;

    const int r0 = tid >> 1, s0 = (tid & 1) * 2;

    wmma::fragment<wmma::accumulator, 16, 16, 16, float> acc[2][4];
    #pragma unroll
    for (int a = 0; a < 2; a++)
        #pragma unroll
        for (int b = 0; b < 4; b++) wmma::fill_fragment(acc[a][b], 0.0f);

    const int NCH = CC / TK;            // 12

    auto issue_copy = [&](int kc, int st) {
        const int k0 = kc * TK;
        const __half* ga = A + (size_t)(m0 + r0) * CC + k0;
        const __half* gb = B + (size_t)(n0 + r0) * CC + k0;
        uint32_t sa = (uint32_t)__cvta_generic_to_shared(stage[st][0] + r0 * SST + s0 * 8);
        cpa16(sa, ga + s0 * 8);
        cpa16(sa + 16, ga + s0 * 8 + 8);
        uint32_t sb = (uint32_t)__cvta_generic_to_shared(stage[st][1] + r0 * SST + s0 * 8);
        cpa16(sb, gb + s0 * 8);
        cpa16(sb + 16, gb + s0 * 8 + 8);
        asm volatile("cp.async.commit_group;" ::: "memory");
    };

    issue_copy(0, 0);

    for (int kc = 0; kc < NCH; kc++) {
        const int cur = kc & 1;
        if (kc + 1 < NCH) {
            issue_copy(kc + 1, cur ^ 1);
            asm volatile("cp.async.wait_group 1;" ::: "memory");
        } else {
            asm volatile("cp.async.wait_group 0;" ::: "memory");
        }
        __syncthreads();
        const __half* sA = stage[cur][0];
        const __half* sB = stage[cur][1];
        #pragma unroll
        for (int kk = 0; kk < TK; kk += 16) {
            wmma::fragment<wmma::matrix_a, 16, 16, 16, __half, wmma::row_major> af[2];
            wmma::fragment<wmma::matrix_b, 16, 16, 16, __half, wmma::col_major> bf[4];
            #pragma unroll
            for (int mi = 0; mi < 2; mi++)
                wmma::load_matrix_sync(af[mi], sA + (wm * 32 + mi * 16) * SST + kk, SST);
            #pragma unroll
            for (int ni = 0; ni < 4; ni++)
                wmma::load_matrix_sync(bf[ni], sB + (wn * 64 + ni * 16) * SST + kk, SST);
            #pragma unroll
            for (int mi = 0; mi < 2; mi++)
                #pragma unroll
                for (int ni = 0; ni < 4; ni++)
                    wmma::mma_sync(acc[mi][ni], af[mi], bf[ni], acc[mi][ni]);
        }
        __syncthreads();
    }

    // epilogue: two 128x64 halves staged in smem
    float* Cs = (float*)smraw;          // 32768 B <= 40960
    #pragma unroll
    for (int half = 0; half < 2; half++) {
        __syncthreads();
        if (wn == half) {
            #pragma unroll
            for (int mi = 0; mi < 2; mi++)
                #pragma unroll
                for (int ni = 0; ni < 4; ni++)
                    wmma::store_matrix_sync(Cs + (wm * 32 + mi * 16) * 64 + ni * 16,
                                            acc[mi][ni], 64, wmma::mem_row_major);
        }
        __syncthreads();
        #pragma unroll
        for (int q = 0; q < 32; q++) {
            int idx = tid + q * 256;
            int r = idx >> 6, c = idx & 63;
            int gcol = n0 + half * 64 + c;
            float val = Cs[idx] + bias[gcol];
            int m = m0 + r;
            if (EPI == 0) {
                Cw[(size_t)m * NN + gcol] = val;
            } else {
                int win = m / LL, l = m % LL;
                int b_ = win >> 6, wr = win & 63;
                int wi = wr >> 3, wj = wr & 7;
                int i = l / 7, j = l % 7;
                size_t orig = (size_t)b_ * (HH * WWD) + (size_t)(wi * 7 + i) * WWD + (wj * 7 + j);
                size_t off = orig * CC + gcol;
                Cw[off] = resid[off] + val;
            }
        }
    }
}

// ---------------- K3: attention, 4-row register blocking + LDS.128 ----------
__global__ void attn_kernel() {
    __shared__ __align__(16) float qs[LL * 36];
    __shared__ __align__(16) float ks[LL * 36];
    __shared__ __align__(16) float vsT[HDIM * 52];
    __shared__ __align__(16) float ss[LL * 52];
    int win = blockIdx.x;
    int head = blockIdx.y;
    int tid = threadIdx.x;              // 128 threads
    const float scale = 0.17677669529663687f;   // 1/sqrt(32)

    for (int idx = tid; idx < LL * 3; idx += 128)
        ss[(idx / 3) * 52 + 49 + idx % 3] = 0.f;
    if (tid < HDIM * 3)
        vsT[(tid / 3) * 52 + 49 + tid % 3] = 0.f;

    const float* base = g_qkv + (size_t)win * LL * C3 + head * HDIM;
    for (int idx = tid; idx < LL * 8; idx += 128) {
        int l = idx >> 3, d4 = (idx & 7) * 4;
        const float* p = base + (size_t)l * C3;
        float4 q4 = *(const float4*)(p + d4);
        float4 k4 = *(const float4*)(p + 384 + d4);
        float4 v4 = *(const float4*)(p + 768 + d4);
        qs[l * 36 + d4 + 0] = q4.x * scale; qs[l * 36 + d4 + 1] = q4.y * scale;
        qs[l * 36 + d4 + 2] = q4.z * scale; qs[l * 36 + d4 + 3] = q4.w * scale;
        ks[l * 36 + d4 + 0] = k4.x; ks[l * 36 + d4 + 1] = k4.y;
        ks[l * 36 + d4 + 2] = k4.z; ks[l * 36 + d4 + 3] = k4.w;
        vsT[(d4 + 0) * 52 + l] = v4.x;
        vsT[(d4 + 1) * 52 + l] = v4.y;
        vsT[(d4 + 2) * 52 + l] = v4.z;
        vsT[(d4 + 3) * 52 + l] = v4.w;
    }
    __syncthreads();

    int warp = tid >> 5, lane = tid & 31;
    bool has2 = lane < 17;
    int j2 = has2 ? (lane + 32) : 48;

    for (int g = warp; g < 13; g += 4) {
        float acc[4][2] = {{0.f,0.f},{0.f,0.f},{0.f,0.f},{0.f,0.f}};
        const float* k0p = ks + lane * 36;
        const float* k1p = ks + j2 * 36;
        #pragma unroll
        for (int d4 = 0; d4 < HDIM; d4 += 4) {
            float4 k0 = *(const float4*)(k0p + d4);
            float4 k1 = *(const float4*)(k1p + d4);
            #pragma unroll
            for (int rr = 0; rr < 4; rr++) {
                int row = g * 4 + rr;
                int rq = row < LL ? row : LL - 1;
                float4 q = *(const float4*)(qs + rq * 36 + d4);
                acc[rr][0] += q.x * k0.x + q.y * k0.y + q.z * k0.z + q.w * k0.w;
                acc[rr][1] += q.x * k1.x + q.y * k1.y + q.z * k1.z + q.w * k1.w;
            }
        }
        #pragma unroll
        for (int rr = 0; rr < 4; rr++) {
            int row = g * 4 + rr;
            if (row < LL) {
                ss[row * 52 + lane] = acc[rr][0];
                if (has2) ss[row * 52 + lane + 32] = acc[rr][1];
            }
        }
    }
    __syncthreads();

    for (int i = warp; i < LL; i += 4) {
        float a = ss[i * 52 + lane];
        float b = has2 ? ss[i * 52 + lane + 32] : -3.0e38f;
        float m = fmaxf(a, b);
        #pragma unroll
        for (int o = 16; o; o >>= 1) m = fmaxf(m, __shfl_xor_sync(0xffffffffu, m, o));
        float e0 = __expf(a - m);
        float e1 = has2 ? __expf(b - m) : 0.f;
        float sm = e0 + e1;
        #pragma unroll
        for (int o = 16; o; o >>= 1) sm += __shfl_xor_sync(0xffffffffu, sm, o);
        float inv = 1.0f / sm;
        ss[i * 52 + lane] = e0 * inv;
        if (has2) ss[i * 52 + lane + 32] = e1 * inv;
    }
    __syncthreads();

    for (int g = warp; g < 13; g += 4) {
        float acc[4] = {0.f, 0.f, 0.f, 0.f};
        const float* vp = vsT + lane * 52;
        #pragma unroll
        for (int j4 = 0; j4 < 52; j4 += 4) {
            float4 v = *(const float4*)(vp + j4);
            #pragma unroll
            for (int rr = 0; rr < 4; rr++) {
                int row = g * 4 + rr;
                int rq = row < LL ? row : LL - 1;
                float4 p = *(const float4*)(ss + rq * 52 + j4);
                acc[rr] += p.x * v.x + p.y * v.y + p.z * v.z + p.w * v.w;
            }
        }
        #pragma unroll
        for (int rr = 0; rr < 4; rr++) {
            int row = g * 4 + rr;
            if (row < LL) {
                size_t off = ((size_t)win * LL + row) * CC + head * HDIM + lane;
                g_a[off] = __float2half(acc[rr]);
            }
        }
    }
}

// ---------------- launch ----------------
extern "C" void kernel_launch(void* const* d_in, const int* in_sizes, int n_in,
                              void* d_out, int out_size) {
    const float* x     = (const float*)d_in[0];
    const float* gamma = (const float*)d_in[1];
    const float* beta  = (const float*)d_in[2];
    const float* w_in  = (const float*)d_in[3];
    const float* b_in  = (const float*)d_in[4];
    const float* w_out = (const float*)d_in[5];
    const float* b_out = (const float*)d_in[6];
    float* out = (float*)d_out;

    cudaFuncSetAttribute(gemm_fp16_kernel<0>,
                         cudaFuncAttributeMaxDynamicSharedMemorySize, GSMEM);
    cudaFuncSetAttribute(gemm_fp16_kernel<1>,
                         cudaFuncAttributeMaxDynamicSharedMemorySize, GSMEM);

    wconv_kernel<<<(C3 * CC + 255) / 256, 256>>>(w_in, w_out);
    ln_window_kernel<<<NTOK, 128>>>(x, gamma, beta);
    gemm_fp16_kernel<0><<<dim3(C3 / 128, NTOK / 128), 256, GSMEM>>>(b_in, nullptr, nullptr);
    attn_kernel<<<dim3(NWIN, NHEAD), 128>>>();
    gemm_fp16_kernel<1><<<dim3(CC / 128, NTOK / 128), 256, GSMEM>>>(b_out, x, out);
}

// round 11
// speedup vs baseline: 2.2607x; 1.1485x over previous
#include <cuda_runtime.h>
#include <cuda_fp16.h>
#include <mma.h>
#include <cstdint>
#include <math.h>

using namespace nvcuda;

// ---------------- static problem dims ----------------
#define BB    32
#define HH    56
#define WWD   56
#define CC    384
#define NTOK  (BB * HH * WWD)      // 100352
#define LL    49
#define NWIN  2048
#define C3    1152
#define NHEAD 12
#define HDIM  32

#define TK    32                    // GEMM K-chunk
#define SST   40                    // GEMM smem row stride (fp16)
#define TILEB (128 * SST * 2)       // 10240 B per tile
#define GSMEM (2 * 2 * TILEB)       // 40960 B dynamic (2 stages x {A,B})

// ---------------- scratch (device globals; no allocs allowed) ----------------
__device__ __half g_yh[(size_t)NTOK * CC];    // LN output fp16, window-ordered
__device__ float  g_qkv[(size_t)NTOK * C3];   // qkv fp32, window-ordered
__device__ __half g_a[(size_t)NTOK * CC];     // attention out fp16
__device__ __half g_wi[(size_t)C3 * CC];      // w_in fp16
__device__ __half g_wo[(size_t)CC * CC];      // w_out fp16

// ---------------- K0: weight fp32 -> fp16 ----------------
__global__ void wconv_kernel(const float* __restrict__ w_in, const float* __restrict__ w_out) {
    int i = blockIdx.x * 256 + threadIdx.x;
    if (i < C3 * CC) g_wi[i] = __float2half(w_in[i]);
    if (i < CC * CC) g_wo[i] = __float2half(w_out[i]);
}

// ---------------- K1: LayerNorm + window partition -> fp16 ----------------
__global__ void ln_window_kernel(const float* __restrict__ x,
                                 const float* __restrict__ gamma,
                                 const float* __restrict__ beta) {
    int t = blockIdx.x;
    int tid = threadIdx.x;              // 128 threads
    const float* xin = x + (size_t)t * CC;
    float v0 = xin[tid], v1 = xin[tid + 128], v2 = xin[tid + 256];
    float s = v0 + v1 + v2;
    float s2 = v0 * v0 + v1 * v1 + v2 * v2;
    #pragma unroll
    for (int o = 16; o; o >>= 1) {
        s  += __shfl_down_sync(0xffffffffu, s, o);
        s2 += __shfl_down_sync(0xffffffffu, s2, o);
    }
    __shared__ float red[2][4];
    int wid = tid >> 5, lane = tid & 31;
    if (lane == 0) { red[0][wid] = s; red[1][wid] = s2; }
    __syncthreads();
    if (tid == 0) {
        float a = red[0][0] + red[0][1] + red[0][2] + red[0][3];
        float b = red[1][0] + red[1][1] + red[1][2] + red[1][3];
        float mu = a * (1.0f / CC);
        float var = b * (1.0f / CC) - mu * mu;
        red[0][0] = mu;
        red[1][0] = rsqrtf(var + 1e-5f);
    }
    __syncthreads();
    float mu = red[0][0], rs = red[1][0];

    int b_ = t / (HH * WWD);
    int n  = t % (HH * WWD);
    int h = n / WWD, w = n % WWD;
    int wi = h / 7, i = h % 7, wj = w / 7, j = w % 7;
    size_t row = (size_t)((b_ * 64 + wi * 8 + wj) * LL + i * 7 + j) * CC;
    #pragma unroll
    for (int q = 0; q < 3; q++) {
        int c = tid + q * 128;
        float v = (q == 0) ? v0 : (q == 1) ? v1 : v2;
        g_yh[row + c] = __float2half((v - mu) * rs * gamma[c] + beta[c]);
    }
}

// ---------------- cp.async helpers ----------------
__device__ __forceinline__ void cpa16(uint32_t saddr, const void* gptr) {
    asm volatile("cp.async.cg.shared.global [%0], [%1], 16;" :: "r"(saddr), "l"(gptr));
}

// ---------------- K2/K4: fp16 wmma GEMM, 128x128, 2-stage cp.async ----------
template <int EPI>
__global__ void __launch_bounds__(256, 2) gemm_fp16_kernel(
        const float* __restrict__ bias,
        const float* __restrict__ resid,
        float* __restrict__ Cout) {
    constexpr int NN = (EPI == 0) ? C3 : CC;
    extern __shared__ __align__(16) char smraw[];
    __half* stage[2][2];
    #pragma unroll
    for (int s = 0; s < 2; s++)
        #pragma unroll
        for (int t = 0; t < 2; t++)
            stage[s][t] = (__half*)(smraw + (s * 2 + t) * TILEB);

    const __half* A = (EPI == 0) ? g_yh : g_a;
    const __half* B = (EPI == 0) ? g_wi : g_wo;
    float* Cw = (EPI == 0) ? g_qkv : Cout;

    const int tid = threadIdx.x;        // 256 threads, 8 warps
    const int warp = tid >> 5;
    const int wm = warp >> 1;
    const int wn = warp & 1;
    const int n0 = blockIdx.x * 128;
    const int m0 = blockIdx.y * 128;

    const int r0 = tid >> 1, s0 = (tid & 1) * 2;

    wmma::fragment<wmma::accumulator, 16, 16, 16, float> acc[2][4];
    #pragma unroll
    for (int a = 0; a < 2; a++)
        #pragma unroll
        for (int b = 0; b < 4; b++) wmma::fill_fragment(acc[a][b], 0.0f);

    const int NCH = CC / TK;            // 12

    auto issue_copy = [&](int kc, int st) {
        const int k0 = kc * TK;
        const __half* ga = A + (size_t)(m0 + r0) * CC + k0;
        const __half* gb = B + (size_t)(n0 + r0) * CC + k0;
        uint32_t sa = (uint32_t)__cvta_generic_to_shared(stage[st][0] + r0 * SST + s0 * 8);
        cpa16(sa, ga + s0 * 8);
        cpa16(sa + 16, ga + s0 * 8 + 8);
        uint32_t sb = (uint32_t)__cvta_generic_to_shared(stage[st][1] + r0 * SST + s0 * 8);
        cpa16(sb, gb + s0 * 8);
        cpa16(sb + 16, gb + s0 * 8 + 8);
        asm volatile("cp.async.commit_group;" ::: "memory");
    };

    issue_copy(0, 0);

    for (int kc = 0; kc < NCH; kc++) {
        const int cur = kc & 1;
        if (kc + 1 < NCH) {
            issue_copy(kc + 1, cur ^ 1);
            asm volatile("cp.async.wait_group 1;" ::: "memory");
        } else {
            asm volatile("cp.async.wait_group 0;" ::: "memory");
        }
        __syncthreads();
        const __half* sA = stage[cur][0];
        const __half* sB = stage[cur][1];
        #pragma unroll
        for (int kk = 0; kk < TK; kk += 16) {
            wmma::fragment<wmma::matrix_a, 16, 16, 16, __half, wmma::row_major> af[2];
            wmma::fragment<wmma::matrix_b, 16, 16, 16, __half, wmma::col_major> bf[4];
            #pragma unroll
            for (int mi = 0; mi < 2; mi++)
                wmma::load_matrix_sync(af[mi], sA + (wm * 32 + mi * 16) * SST + kk, SST);
            #pragma unroll
            for (int ni = 0; ni < 4; ni++)
                wmma::load_matrix_sync(bf[ni], sB + (wn * 64 + ni * 16) * SST + kk, SST);
            #pragma unroll
            for (int mi = 0; mi < 2; mi++)
                #pragma unroll
                for (int ni = 0; ni < 4; ni++)
                    wmma::mma_sync(acc[mi][ni], af[mi], bf[ni], acc[mi][ni]);
        }
        __syncthreads();
    }

    float* Cs = (float*)smraw;
    #pragma unroll
    for (int half = 0; half < 2; half++) {
        __syncthreads();
        if (wn == half) {
            #pragma unroll
            for (int mi = 0; mi < 2; mi++)
                #pragma unroll
                for (int ni = 0; ni < 4; ni++)
                    wmma::store_matrix_sync(Cs + (wm * 32 + mi * 16) * 64 + ni * 16,
                                            acc[mi][ni], 64, wmma::mem_row_major);
        }
        __syncthreads();
        #pragma unroll
        for (int q = 0; q < 32; q++) {
            int idx = tid + q * 256;
            int r = idx >> 6, c = idx & 63;
            int gcol = n0 + half * 64 + c;
            float val = Cs[idx] + bias[gcol];
            int m = m0 + r;
            if (EPI == 0) {
                Cw[(size_t)m * NN + gcol] = val;
            } else {
                int win = m / LL, l = m % LL;
                int b_ = win >> 6, wr = win & 63;
                int wi = wr >> 3, wj = wr & 7;
                int i = l / 7, j = l % 7;
                size_t orig = (size_t)b_ * (HH * WWD) + (size_t)(wi * 7 + i) * WWD + (wj * 7 + j);
                size_t off = orig * CC + gcol;
                Cw[off] = resid[off] + val;
            }
        }
    }
}

// ---------------- K3: attention via fp16 wmma (pad L 49->64) ----------------
// sQ/sK/sV: [64][40] fp16; sS: [64][68] fp32; sP: [64][72] fp16.
// S = Q.K^T (4 warps x m-tile), scalar softmax, O = P.V, stage out via sS[.][36].
__global__ void attn_kernel() {
    __shared__ __align__(16) __half sQ[64 * 40];
    __shared__ __align__(16) __half sK[64 * 40];
    __shared__ __align__(16) __half sV[64 * 40];
    __shared__ __align__(16) float  sS[64 * 68];
    __shared__ __align__(16) __half sP[64 * 72];
    int win = blockIdx.x;
    int head = blockIdx.y;
    int tid = threadIdx.x;              // 128 threads, 4 warps
    int warp = tid >> 5, lane = tid & 31;
    const float scale = 0.17677669529663687f;   // 1/sqrt(32)

    // zero P entirely (pad cols must be exact 0) and V pad rows (kill 0*NaN)
    #pragma unroll
    for (int q = 0; q < 18; q++) ((uint32_t*)sP)[tid + q * 128] = 0u;   // 64*72/2 = 2304
    for (int idx = tid; idx < 15 * 20; idx += 128)                      // rows 49..63, 40 halves
        ((uint32_t*)(sV + 49 * 40))[idx] = 0u;

    const float* base = g_qkv + (size_t)win * LL * C3 + head * HDIM;
    for (int idx = tid; idx < LL * 8; idx += 128) {
        int l = idx >> 3, d4 = (idx & 7) * 4;
        const float* p = base + (size_t)l * C3;
        float4 q4 = *(const float4*)(p + d4);
        float4 k4 = *(const float4*)(p + 384 + d4);
        float4 v4 = *(const float4*)(p + 768 + d4);
        sQ[l * 40 + d4 + 0] = __float2half(q4.x * scale);
        sQ[l * 40 + d4 + 1] = __float2half(q4.y * scale);
        sQ[l * 40 + d4 + 2] = __float2half(q4.z * scale);
        sQ[l * 40 + d4 + 3] = __float2half(q4.w * scale);
        sK[l * 40 + d4 + 0] = __float2half(k4.x);
        sK[l * 40 + d4 + 1] = __float2half(k4.y);
        sK[l * 40 + d4 + 2] = __float2half(k4.z);
        sK[l * 40 + d4 + 3] = __float2half(k4.w);
        sV[l * 40 + d4 + 0] = __float2half(v4.x);
        sV[l * 40 + d4 + 1] = __float2half(v4.y);
        sV[l * 40 + d4 + 2] = __float2half(v4.z);
        sV[l * 40 + d4 + 3] = __float2half(v4.w);
    }
    __syncthreads();

    // ---- S = Q.K^T : warp w -> rows 16w..16w+15, 4 n-tiles, 2 k-steps ----
    {
        wmma::fragment<wmma::accumulator, 16, 16, 16, float> sacc[4];
        #pragma unroll
        for (int n = 0; n < 4; n++) wmma::fill_fragment(sacc[n], 0.0f);
        #pragma unroll
        for (int k = 0; k < 2; k++) {
            wmma::fragment<wmma::matrix_a, 16, 16, 16, __half, wmma::row_major> af;
            wmma::load_matrix_sync(af, sQ + warp * 16 * 40 + k * 16, 40);
            #pragma unroll
            for (int n = 0; n < 4; n++) {
                wmma::fragment<wmma::matrix_b, 16, 16, 16, __half, wmma::col_major> bf;
                wmma::load_matrix_sync(bf, sK + n * 16 * 40 + k * 16, 40);
                wmma::mma_sync(sacc[n], af, bf, sacc[n]);
            }
        }
        #pragma unroll
        for (int n = 0; n < 4; n++)
            wmma::store_matrix_sync(sS + warp * 16 * 68 + n * 16, sacc[n], 68, wmma::mem_row_major);
    }
    __syncthreads();

    // ---- softmax rows 0..48 (cols 0..48), write P fp16 ----
    bool has2 = lane < 17;
    for (int i = warp; i < LL; i += 4) {
        float a = sS[i * 68 + lane];
        float b = has2 ? sS[i * 68 + lane + 32] : -3.0e38f;
        float m = fmaxf(a, b);
        #pragma unroll
        for (int o = 16; o; o >>= 1) m = fmaxf(m, __shfl_xor_sync(0xffffffffu, m, o));
        float e0 = __expf(a - m);
        float e1 = has2 ? __expf(b - m) : 0.f;
        float sm = e0 + e1;
        #pragma unroll
        for (int o = 16; o; o >>= 1) sm += __shfl_xor_sync(0xffffffffu, sm, o);
        float inv = 1.0f / sm;
        sP[i * 72 + lane] = __float2half(e0 * inv);
        if (has2) sP[i * 72 + lane + 32] = __float2half(e1 * inv);
    }
    __syncthreads();

    // ---- O = P.V : warp w -> rows 16w..16w+15, 2 n-tiles, 4 k-steps ----
    {
        wmma::fragment<wmma::accumulator, 16, 16, 16, float> oacc[2];
        #pragma unroll
        for (int n = 0; n < 2; n++) wmma::fill_fragment(oacc[n], 0.0f);
        #pragma unroll
        for (int k = 0; k < 4; k++) {
            wmma::fragment<wmma::matrix_a, 16, 16, 16, __half, wmma::row_major> pf;
            wmma::load_matrix_sync(pf, sP + warp * 16 * 72 + k * 16, 72);
            #pragma unroll
            for (int n = 0; n < 2; n++) {
                wmma::fragment<wmma::matrix_b, 16, 16, 16, __half, wmma::row_major> vf;
                wmma::load_matrix_sync(vf, sV + k * 16 * 40 + n * 16, 40);
                wmma::mma_sync(oacc[n], pf, vf, oacc[n]);
            }
        }
        #pragma unroll
        for (int n = 0; n < 2; n++)
            wmma::store_matrix_sync(sS + warp * 16 * 36 + n * 16, oacc[n], 36, wmma::mem_row_major);
    }
    __syncthreads();

    // ---- write O rows 0..48 ----
    for (int idx = tid; idx < LL * HDIM; idx += 128) {
        int row = idx >> 5, col = idx & 31;
        g_a[((size_t)win * LL + row) * CC + head * HDIM + col] =
            __float2half(sS[row * 36 + col]);
    }
}

// ---------------- launch ----------------
extern "C" void kernel_launch(void* const* d_in, const int* in_sizes, int n_in,
                              void* d_out, int out_size) {
    const float* x     = (const float*)d_in[0];
    const float* gamma = (const float*)d_in[1];
    const float* beta  = (const float*)d_in[2];
    const float* w_in  = (const float*)d_in[3];
    const float* b_in  = (const float*)d_in[4];
    const float* w_out = (const float*)d_in[5];
    const float* b_out = (const float*)d_in[6];
    float* out = (float*)d_out;

    cudaFuncSetAttribute(gemm_fp16_kernel<0>,
                         cudaFuncAttributeMaxDynamicSharedMemorySize, GSMEM);
    cudaFuncSetAttribute(gemm_fp16_kernel<1>,
                         cudaFuncAttributeMaxDynamicSharedMemorySize, GSMEM);

    wconv_kernel<<<(C3 * CC + 255) / 256, 256>>>(w_in, w_out);
    ln_window_kernel<<<NTOK, 128>>>(x, gamma, beta);
    gemm_fp16_kernel<0><<<dim3(C3 / 128, NTOK / 128), 256, GSMEM>>>(b_in, nullptr, nullptr);
    attn_kernel<<<dim3(NWIN, NHEAD), 128>>>();
    gemm_fp16_kernel<1><<<dim3(CC / 128, NTOK / 128), 256, GSMEM>>>(b_out, x, out);
}

// round 13
// speedup vs baseline: 2.4857x; 1.0995x over previous
#include <cuda_runtime.h>
#include <cuda_fp16.h>
#include <mma.h>
#include <cstdint>
#include <math.h>

using namespace nvcuda;

// ---------------- static problem dims ----------------
#define BB    32
#define HH    56
#define WWD   56
#define CC    384
#define NTOK  (BB * HH * WWD)      // 100352
#define LL    49
#define NWIN  2048
#define C3    1152
#define NHEAD 12
#define HDIM  32

#define TK    32                    // GEMM K-chunk
#define SST   40                    // GEMM smem row stride (fp16)
#define TILEB (128 * SST * 2)       // 10240 B per tile
#define GSMEM (2 * 2 * TILEB)       // 40960 B dynamic (2 stages x {A,B})

// ---------------- scratch (device globals; no allocs allowed) ----------------
__device__ __half g_yh[(size_t)NTOK * CC];    // LN output fp16, window-ordered
__device__ __half g_qkvh[(size_t)NTOK * C3];  // qkv fp16, window-ordered
__device__ __half g_a[(size_t)NTOK * CC];     // attention out fp16
__device__ __half g_wi[(size_t)C3 * CC];      // w_in fp16
__device__ __half g_wo[(size_t)CC * CC];      // w_out fp16

// ---------------- K0: weight fp32 -> fp16 ----------------
__global__ void wconv_kernel(const float* __restrict__ w_in, const float* __restrict__ w_out) {
    int i = blockIdx.x * 256 + threadIdx.x;
    if (i < C3 * CC) g_wi[i] = __float2half(w_in[i]);
    if (i < CC * CC) g_wo[i] = __float2half(w_out[i]);
}

// ---------------- K1: LayerNorm + window partition -> fp16 ----------------
__global__ void ln_window_kernel(const float* __restrict__ x,
                                 const float* __restrict__ gamma,
                                 const float* __restrict__ beta) {
    int t = blockIdx.x;
    int tid = threadIdx.x;              // 128 threads
    const float* xin = x + (size_t)t * CC;
    float v0 = xin[tid], v1 = xin[tid + 128], v2 = xin[tid + 256];
    float s = v0 + v1 + v2;
    float s2 = v0 * v0 + v1 * v1 + v2 * v2;
    #pragma unroll
    for (int o = 16; o; o >>= 1) {
        s  += __shfl_down_sync(0xffffffffu, s, o);
        s2 += __shfl_down_sync(0xffffffffu, s2, o);
    }
    __shared__ float red[2][4];
    int wid = tid >> 5, lane = tid & 31;
    if (lane == 0) { red[0][wid] = s; red[1][wid] = s2; }
    __syncthreads();
    if (tid == 0) {
        float a = red[0][0] + red[0][1] + red[0][2] + red[0][3];
        float b = red[1][0] + red[1][1] + red[1][2] + red[1][3];
        float mu = a * (1.0f / CC);
        float var = b * (1.0f / CC) - mu * mu;
        red[0][0] = mu;
        red[1][0] = rsqrtf(var + 1e-5f);
    }
    __syncthreads();
    float mu = red[0][0], rs = red[1][0];

    int b_ = t / (HH * WWD);
    int n  = t % (HH * WWD);
    int h = n / WWD, w = n % WWD;
    int wi = h / 7, i = h % 7, wj = w / 7, j = w % 7;
    size_t row = (size_t)((b_ * 64 + wi * 8 + wj) * LL + i * 7 + j) * CC;
    #pragma unroll
    for (int q = 0; q < 3; q++) {
        int c = tid + q * 128;
        float v = (q == 0) ? v0 : (q == 1) ? v1 : v2;
        g_yh[row + c] = __float2half((v - mu) * rs * gamma[c] + beta[c]);
    }
}

// ---------------- cp.async helpers ----------------
__device__ __forceinline__ void cpa16(uint32_t saddr, const void* gptr) {
    asm volatile("cp.async.cg.shared.global [%0], [%1], 16;" :: "r"(saddr), "l"(gptr));
}

// ---------------- K2/K4: fp16 wmma GEMM, 128x128, 2-stage cp.async ----------
// EPI==0: A=g_yh, B=g_wi, N=1152, write g_qkvh fp16 (+bias)
// EPI==1: A=g_a,  B=g_wo, N=384,  write d_out fp32 (+bias, reverse, residual)
template <int EPI>
__global__ void __launch_bounds__(256, 2) gemm_fp16_kernel(
        const float* __restrict__ bias,
        const float* __restrict__ resid,
        float* __restrict__ Cout) {
    extern __shared__ __align__(16) char smraw[];
    __half* stage[2][2];
    #pragma unroll
    for (int s = 0; s < 2; s++)
        #pragma unroll
        for (int t = 0; t < 2; t++)
            stage[s][t] = (__half*)(smraw + (s * 2 + t) * TILEB);

    const __half* A = (EPI == 0) ? g_yh : g_a;
    const __half* B = (EPI == 0) ? g_wi : g_wo;

    const int tid = threadIdx.x;        // 256 threads, 8 warps
    const int warp = tid >> 5;
    const int wm = warp >> 1;
    const int wn = warp & 1;
    const int n0 = blockIdx.x * 128;
    const int m0 = blockIdx.y * 128;

    const int r0 = tid >> 1, s0 = (tid & 1) * 2;

    wmma::fragment<wmma::accumulator, 16, 16, 16, float> acc[2][4];
    #pragma unroll
    for (int a = 0; a < 2; a++)
        #pragma unroll
        for (int b = 0; b < 4; b++) wmma::fill_fragment(acc[a][b], 0.0f);

    const int NCH = CC / TK;            // 12

    auto issue_copy = [&](int kc, int st) {
        const int k0 = kc * TK;
        const __half* ga = A + (size_t)(m0 + r0) * CC + k0;
        const __half* gb = B + (size_t)(n0 + r0) * CC + k0;
        uint32_t sa = (uint32_t)__cvta_generic_to_shared(stage[st][0] + r0 * SST + s0 * 8);
        cpa16(sa, ga + s0 * 8);
        cpa16(sa + 16, ga + s0 * 8 + 8);
        uint32_t sb = (uint32_t)__cvta_generic_to_shared(stage[st][1] + r0 * SST + s0 * 8);
        cpa16(sb, gb + s0 * 8);
        cpa16(sb + 16, gb + s0 * 8 + 8);
        asm volatile("cp.async.commit_group;" ::: "memory");
    };

    issue_copy(0, 0);

    for (int kc = 0; kc < NCH; kc++) {
        const int cur = kc & 1;
        if (kc + 1 < NCH) {
            issue_copy(kc + 1, cur ^ 1);
            asm volatile("cp.async.wait_group 1;" ::: "memory");
        } else {
            asm volatile("cp.async.wait_group 0;" ::: "memory");
        }
        __syncthreads();
        const __half* sA = stage[cur][0];
        const __half* sB = stage[cur][1];
        #pragma unroll
        for (int kk = 0; kk < TK; kk += 16) {
            wmma::fragment<wmma::matrix_a, 16, 16, 16, __half, wmma::row_major> af[2];
            wmma::fragment<wmma::matrix_b, 16, 16, 16, __half, wmma::col_major> bf[4];
            #pragma unroll
            for (int mi = 0; mi < 2; mi++)
                wmma::load_matrix_sync(af[mi], sA + (wm * 32 + mi * 16) * SST + kk, SST);
            #pragma unroll
            for (int ni = 0; ni < 4; ni++)
                wmma::load_matrix_sync(bf[ni], sB + (wn * 64 + ni * 16) * SST + kk, SST);
            #pragma unroll
            for (int mi = 0; mi < 2; mi++)
                #pragma unroll
                for (int ni = 0; ni < 4; ni++)
                    wmma::mma_sync(acc[mi][ni], af[mi], bf[ni], acc[mi][ni]);
        }
        __syncthreads();
    }

    float* Cs = (float*)smraw;
    #pragma unroll
    for (int half = 0; half < 2; half++) {
        __syncthreads();
        if (wn == half) {
            #pragma unroll
            for (int mi = 0; mi < 2; mi++)
                #pragma unroll
                for (int ni = 0; ni < 4; ni++)
                    wmma::store_matrix_sync(Cs + (wm * 32 + mi * 16) * 64 + ni * 16,
                                            acc[mi][ni], 64, wmma::mem_row_major);
        }
        __syncthreads();
        if (EPI == 0) {
            // fp16 out, half2 stores
            #pragma unroll
            for (int q = 0; q < 16; q++) {
                int idx = tid + q * 256;        // 4096 half2 positions
                int r = idx >> 5, c2 = (idx & 31) * 2;
                int gcol = n0 + half * 64 + c2;
                float vx = Cs[r * 64 + c2]     + bias[gcol];
                float vy = Cs[r * 64 + c2 + 1] + bias[gcol + 1];
                *(__half2*)(g_qkvh + (size_t)(m0 + r) * C3 + gcol) =
                    __floats2half2_rn(vx, vy);
            }
        } else {
            #pragma unroll
            for (int q = 0; q < 32; q++) {
                int idx = tid + q * 256;
                int r = idx >> 6, c = idx & 63;
                int gcol = n0 + half * 64 + c;
                float val = Cs[idx] + bias[gcol];
                int m = m0 + r;
                int win = m / LL, l = m % LL;
                int b_ = win >> 6, wr = win & 63;
                int wi = wr >> 3, wj = wr & 7;
                int i = l / 7, j = l % 7;
                size_t orig = (size_t)b_ * (HH * WWD) + (size_t)(wi * 7 + i) * WWD + (wj * 7 + j);
                size_t off = orig * CC + gcol;
                Cout[off] = resid[off] + val;
            }
        }
    }
}

// ---------------- K3: attention via fp16 wmma, fp16 qkv, aliased smem -------
// layout (bytes): sQ 0..5120, sK 5120..10240, sV 10240..15360,
//                 sS 15360..32768 (64x68 fp32); sP aliases [0..9216) after S.
__global__ void attn_kernel() {
    __shared__ __align__(16) char sm[32768];
    __half* sQ = (__half*)sm;
    __half* sK = (__half*)(sm + 5120);
    __half* sV = (__half*)(sm + 10240);
    float*  sS = (float*)(sm + 15360);
    __half* sP = (__half*)sm;           // overlays Q/K once consumed
    int win = blockIdx.x;
    int head = blockIdx.y;
    int tid = threadIdx.x;              // 128 threads, 4 warps
    int warp = tid >> 5, lane = tid & 31;

    // zero V pad rows 49..63 (kill 0*garbage in P.V)
    for (int idx = tid; idx < 15 * 20; idx += 128)
        ((uint32_t*)(sV + 49 * 40))[idx] = 0u;

    const __half* base = g_qkvh + (size_t)win * LL * C3 + head * HDIM;
    const __half2 sc2 = __float2half2_rn(0.17677669529663687f);  // 1/sqrt(32)
    for (int idx = tid; idx < LL * 4; idx += 128) {
        int l = idx >> 2, d8 = (idx & 3) * 8;
        const __half* p = base + (size_t)l * C3 + d8;
        uint4 q4 = *(const uint4*)(p);
        uint4 k4 = *(const uint4*)(p + 384);
        uint4 v4 = *(const uint4*)(p + 768);
        __half2* qh = (__half2*)&q4;
        #pragma unroll
        for (int e = 0; e < 4; e++) qh[e] = __hmul2(qh[e], sc2);
        *(uint4*)(sQ + l * 40 + d8) = q4;
        *(uint4*)(sK + l * 40 + d8) = k4;
        *(uint4*)(sV + l * 40 + d8) = v4;
    }
    __syncthreads();

    // ---- S = Q.K^T : warp w -> rows 16w..16w+15 ----
    {
        wmma::fragment<wmma::accumulator, 16, 16, 16, float> sacc[4];
        #pragma unroll
        for (int n = 0; n < 4; n++) wmma::fill_fragment(sacc[n], 0.0f);
        #pragma unroll
        for (int k = 0; k < 2; k++) {
            wmma::fragment<wmma::matrix_a, 16, 16, 16, __half, wmma::row_major> af;
            wmma::load_matrix_sync(af, sQ + warp * 16 * 40 + k * 16, 40);
            #pragma unroll
            for (int n = 0; n < 4; n++) {
                wmma::fragment<wmma::matrix_b, 16, 16, 16, __half, wmma::col_major> bf;
                wmma::load_matrix_sync(bf, sK + n * 16 * 40 + k * 16, 40);
                wmma::mma_sync(sacc[n], af, bf, sacc[n]);
            }
        }
        #pragma unroll
        for (int n = 0; n < 4; n++)
            wmma::store_matrix_sync(sS + warp * 16 * 68 + n * 16, sacc[n], 68, wmma::mem_row_major);
    }
    __syncthreads();

    // zero P fully (aliases Q/K, now dead): 64*72*2/4 = 2304 words
    #pragma unroll
    for (int q = 0; q < 18; q++) ((uint32_t*)sP)[tid + q * 128] = 0u;
    __syncthreads();

    // ---- softmax rows 0..48 (cols 0..48), write P fp16 ----
    bool has2 = lane < 17;
    for (int i = warp; i < LL; i += 4) {
        float a = sS[i * 68 + lane];
        float b = has2 ? sS[i * 68 + lane + 32] : -3.0e38f;
        float m = fmaxf(a, b);
        #pragma unroll
        for (int o = 16; o; o >>= 1) m = fmaxf(m, __shfl_xor_sync(0xffffffffu, m, o));
        float e0 = __expf(a - m);
        float e1 = has2 ? __expf(b - m) : 0.f;
        float sm_ = e0 + e1;
        #pragma unroll
        for (int o = 16; o; o >>= 1) sm_ += __shfl_xor_sync(0xffffffffu, sm_, o);
        float inv = 1.0f / sm_;
        sP[i * 72 + lane] = __float2half(e0 * inv);
        if (has2) sP[i * 72 + lane + 32] = __float2half(e1 * inv);
    }
    __syncthreads();

    // ---- O = P.V : warp w -> rows 16w..16w+15; stage out via sS (ldm 36) ----
    {
        wmma::fragment<wmma::accumulator, 16, 16, 16, float> oacc[2];
        #pragma unroll
        for (int n = 0; n < 2; n++) wmma::fill_fragment(oacc[n], 0.0f);
        #pragma unroll
        for (int k = 0; k < 4; k++) {
            wmma::fragment<wmma::matrix_a, 16, 16, 16, __half, wmma::row_major> pf;
            wmma::load_matrix_sync(pf, sP + warp * 16 * 72 + k * 16, 72);
            #pragma unroll
            for (int n = 0; n < 2; n++) {
                wmma::fragment<wmma::matrix_b, 16, 16, 16, __half, wmma::row_major> vf;
                wmma::load_matrix_sync(vf, sV + k * 16 * 40 + n * 16, 40);
                wmma::mma_sync(oacc[n], pf, vf, oacc[n]);
            }
        }
        #pragma unroll
        for (int n = 0; n < 2; n++)
            wmma::store_matrix_sync(sS + warp * 16 * 36 + n * 16, oacc[n], 36, wmma::mem_row_major);
    }
    __syncthreads();

    // ---- write O rows 0..48 ----
    for (int idx = tid; idx < LL * HDIM; idx += 128) {
        int row = idx >> 5, col = idx & 31;
        g_a[((size_t)win * LL + row) * CC + head * HDIM + col] =
            __float2half(sS[row * 36 + col]);
    }
}

// ---------------- launch ----------------
extern "C" void kernel_launch(void* const* d_in, const int* in_sizes, int n_in,
                              void* d_out, int out_size) {
    const float* x     = (const float*)d_in[0];
    const float* gamma = (const float*)d_in[1];
    const float* beta  = (const float*)d_in[2];
    const float* w_in  = (const float*)d_in[3];
    const float* b_in  = (const float*)d_in[4];
    const float* w_out = (const float*)d_in[5];
    const float* b_out = (const float*)d_in[6];
    float* out = (float*)d_out;

    cudaFuncSetAttribute(gemm_fp16_kernel<0>,
                         cudaFuncAttributeMaxDynamicSharedMemorySize, GSMEM);
    cudaFuncSetAttribute(gemm_fp16_kernel<1>,
                         cudaFuncAttributeMaxDynamicSharedMemorySize, GSMEM);

    wconv_kernel<<<(C3 * CC + 255) / 256, 256>>>(w_in, w_out);
    ln_window_kernel<<<NTOK, 128>>>(x, gamma, beta);
    gemm_fp16_kernel<0><<<dim3(C3 / 128, NTOK / 128), 256, GSMEM>>>(b_in, nullptr, nullptr);
    attn_kernel<<<dim3(NWIN, NHEAD), 128>>>();
    gemm_fp16_kernel<1><<<dim3(CC / 128, NTOK / 128), 256, GSMEM>>>(b_out, x, out);
}